// round 15
// baseline (speedup 1.0000x reference)
#include <cuda_runtime.h>
#include <math.h>
#include <stdint.h>

// ---------------- problem constants ----------------
#define BB 4
#define SS 2048
#define DD 512
#define HH 8
#define DHEAD 64
#define DFF 2048
#define NTOK (BB*SS)          // 8192 tokens
#define NT (NTOK*DD)          // 4194304 floats per [tokens, 512] buffer

// ---------------- scratch ----------------
// 12 NT buffers + WQr/WKr/WVr + Wqkv + bqkv + split-K partials (reused as Lpart)
__device__ float g_scratch[12*(size_t)NT + 6*DD*DD + 2048 + 12*DD*DD];

// ---------------- helpers ----------------
__device__ __forceinline__ uint32_t f2tf(float x) {
    uint32_t u;
    asm("cvt.rna.tf32.f32 %0, %1;" : "=r"(u) : "f"(x));
    return u;
}

__device__ __forceinline__ float ex2(float x) {
    float y;
    asm("ex2.approx.f32 %0, %1;" : "=f"(y) : "f"(x));
    return y;
}

#define MMA_TF32(d, a0, a1, a2, a3, b0, b1)                                \
    asm volatile("mma.sync.aligned.m16n8k8.row.col.f32.tf32.tf32.f32 "     \
        "{%0,%1,%2,%3}, {%4,%5,%6,%7}, {%8,%9}, {%0,%1,%2,%3};"            \
        : "+f"(d[0]), "+f"(d[1]), "+f"(d[2]), "+f"(d[3])                   \
        : "r"(a0), "r"(a1), "r"(a2), "r"(a3), "r"(b0), "r"(b1))

// scale folded into Q at GEMM epilogue: 1/sqrt(64) * log2(e)
#define QSCALE 0.180336880f

// ---------------- embedding + inline PE, batch-amortized (tf32 out) ---------
__global__ void embed_pe_kernel(const int* __restrict__ x, const float* __restrict__ emb,
                                float* __restrict__ z)
{
    int idx = blockIdx.x * blockDim.x + threadIdx.x;   // over SS*DD
    if (idx >= SS * DD) return;
    int d = idx & (DD - 1);
    int s = idx >> 9;
    float di = (float)d * (1.0f / (float)DD);
    float ang = (float)s / powf(10000.0f, di);
    float pe = (d & 1) ? cosf(ang) : sinf(ang);
#pragma unroll
    for (int b = 0; b < BB; b++) {
        int t = b * SS + s;
        z[(size_t)t * DD + d] = __uint_as_float(f2tf(emb[(size_t)x[t] * DD + d] + pe));
    }
}

// ---------------- merged repack: 3 per-head weights -> tf32 -----------------
__global__ void repack3_kernel(const float* __restrict__ WQ, const float* __restrict__ WK,
                               const float* __restrict__ WV,
                               float* __restrict__ WQr, float* __restrict__ WKr,
                               float* __restrict__ WVr)
{
    int gidx = blockIdx.x * blockDim.x + threadIdx.x;
    if (gidx >= 3 * DD * DD) return;
    int which = gidx / (DD * DD);
    int idx = gidx - which * (DD * DD);
    const float* W = (which == 0) ? WQ : (which == 1) ? WK : WV;
    float* Wr = (which == 0) ? WQr : (which == 1) ? WKr : WVr;
    int n = idx & (DD - 1);
    int d = idx >> 9;
    int h = n >> 6, k = n & 63;
    Wr[idx] = __uint_as_float(f2tf(W[((size_t)h * DD + d) * DHEAD + k]));
}

// ---------------- merged composed bias ------
__global__ void bias_compose3_kernel(
    const float* __restrict__ bfQ, const float* __restrict__ bfK, const float* __restrict__ bfV,
    const float* __restrict__ WQr, const float* __restrict__ WKr, const float* __restrict__ WVr,
    const float* __restrict__ bQ,  const float* __restrict__ bK,  const float* __restrict__ bV,
    float* __restrict__ out)
{
    int g = blockIdx.x * blockDim.x + threadIdx.x;
    if (g >= 3 * DD) return;
    int which = g >> 9;
    int n = g & (DD - 1);
    const float* bf = (which == 0) ? bfQ : (which == 1) ? bfK : bfV;
    const float* Wr = (which == 0) ? WQr : (which == 1) ? WKr : WVr;
    const float* bh = (which == 0) ? bQ : (which == 1) ? bK : bV;
    float s = bh[n];
    for (int k = 0; k < DD; k++)
        s += bf[k] * Wr[(size_t)k * DD + n];
    out[g] = s;
}

// ---------------- tf32 tensor-core GEMM (cvt-in-staging) --------------------
#define GS_A 20
#define GS_B 136

__global__ __launch_bounds__(256, 2) void gemm_tf32_kernel(
    int M, int N, int K, int ldc,
    const float* __restrict__ A, const float* __restrict__ W,
    const float* __restrict__ bias, float* __restrict__ C, int mode)
{
    __shared__ uint32_t As[128 * GS_A];
    __shared__ uint32_t Bs[16 * GS_B];

    const int tid  = threadIdx.x;
    const int warp = tid >> 5;
    const int lane = tid & 31;
    const int qr   = lane >> 2;
    const int qc   = lane & 3;
    const int wm   = warp & 1;
    const int wn   = warp >> 1;
    const int m0   = blockIdx.y * 128;
    const int n0   = blockIdx.x * 128;

    float acc[4][4][4];
#pragma unroll
    for (int i = 0; i < 4; i++)
#pragma unroll
        for (int j = 0; j < 4; j++)
#pragma unroll
            for (int c = 0; c < 4; c++) acc[i][j][c] = 0.f;

    float4 ar[2], br[2];
#pragma unroll
    for (int p = 0; p < 2; p++) {
        int idx = p * 256 + tid;
        int arow = idx >> 2, ac = (idx & 3) * 4;
        ar[p] = *(const float4*)&A[(size_t)(m0 + arow) * K + ac];
        int krow = idx >> 5, nc = (idx & 31) * 4;
        br[p] = *(const float4*)&W[(size_t)krow * N + n0 + nc];
    }

    for (int k0 = 0; k0 < K; k0 += 16) {
        __syncthreads();
#pragma unroll
        for (int p = 0; p < 2; p++) {
            int idx = p * 256 + tid;
            int arow = idx >> 2, ac = (idx & 3) * 4;
            As[arow * GS_A + ac + 0] = f2tf(ar[p].x);
            As[arow * GS_A + ac + 1] = f2tf(ar[p].y);
            As[arow * GS_A + ac + 2] = f2tf(ar[p].z);
            As[arow * GS_A + ac + 3] = f2tf(ar[p].w);
            int krow = idx >> 5, nc = (idx & 31) * 4;
            Bs[krow * GS_B + nc + 0] = f2tf(br[p].x);
            Bs[krow * GS_B + nc + 1] = f2tf(br[p].y);
            Bs[krow * GS_B + nc + 2] = f2tf(br[p].z);
            Bs[krow * GS_B + nc + 3] = f2tf(br[p].w);
        }
        __syncthreads();

        if (k0 + 16 < K) {
#pragma unroll
            for (int p = 0; p < 2; p++) {
                int idx = p * 256 + tid;
                int arow = idx >> 2, ac = (idx & 3) * 4;
                ar[p] = *(const float4*)&A[(size_t)(m0 + arow) * K + k0 + 16 + ac];
                int krow = idx >> 5, nc = (idx & 31) * 4;
                br[p] = *(const float4*)&W[(size_t)(k0 + 16 + krow) * N + n0 + nc];
            }
        }

#pragma unroll
        for (int kk = 0; kk < 16; kk += 8) {
            uint32_t af[4][4], bf[4][2];
#pragma unroll
            for (int mt = 0; mt < 4; mt++) {
                int mrow = wm * 64 + mt * 16 + qr;
                af[mt][0] = As[mrow * GS_A + kk + qc];
                af[mt][1] = As[(mrow + 8) * GS_A + kk + qc];
                af[mt][2] = As[mrow * GS_A + kk + qc + 4];
                af[mt][3] = As[(mrow + 8) * GS_A + kk + qc + 4];
            }
#pragma unroll
            for (int nt = 0; nt < 4; nt++) {
                int ncol = wn * 32 + nt * 8 + qr;
                bf[nt][0] = Bs[(kk + qc) * GS_B + ncol];
                bf[nt][1] = Bs[(kk + qc + 4) * GS_B + ncol];
            }
#pragma unroll
            for (int mt = 0; mt < 4; mt++)
#pragma unroll
                for (int nt = 0; nt < 4; nt++)
                    MMA_TF32(acc[mt][nt], af[mt][0], af[mt][1], af[mt][2], af[mt][3],
                             bf[nt][0], bf[nt][1]);
        }
    }

    // epilogue
#pragma unroll
    for (int mt = 0; mt < 4; mt++) {
        int row = m0 + wm * 64 + mt * 16 + qr;
#pragma unroll
        for (int nt = 0; nt < 4; nt++) {
            int col = n0 + wn * 32 + nt * 8 + qc * 2;
            float2 bv = bias ? *(const float2*)&bias[col] : make_float2(0.f, 0.f);
            float2 v0, v1;
            v0.x = acc[mt][nt][0] + bv.x;
            v0.y = acc[mt][nt][1] + bv.y;
            v1.x = acc[mt][nt][2] + bv.x;
            v1.y = acc[mt][nt][3] + bv.y;
            if (mode == 1) {
                v0.x = __uint_as_float(f2tf(fmaxf(v0.x, 0.f)));
                v0.y = __uint_as_float(f2tf(fmaxf(v0.y, 0.f)));
                v1.x = __uint_as_float(f2tf(fmaxf(v1.x, 0.f)));
                v1.y = __uint_as_float(f2tf(fmaxf(v1.y, 0.f)));
            } else if (mode == 2) {
                float sc = (col < DD) ? QSCALE : 1.0f;
                v0.x = __uint_as_float(f2tf(v0.x * sc));
                v0.y = __uint_as_float(f2tf(v0.y * sc));
                v1.x = __uint_as_float(f2tf(v1.x * sc));
                v1.y = __uint_as_float(f2tf(v1.y * sc));
            } else if (mode == 3) {
                v0.x = __uint_as_float(f2tf(v0.x));
                v0.y = __uint_as_float(f2tf(v0.y));
                v1.x = __uint_as_float(f2tf(v1.x));
                v1.y = __uint_as_float(f2tf(v1.y));
            }
            *(float2*)&C[(size_t)row * ldc + col] = v0;
            *(float2*)&C[(size_t)(row + 8) * ldc + col] = v1;
        }
    }
}

// ---------------- split-K compose GEMM ------------------------
__global__ __launch_bounds__(256, 2) void gemm_compose_splitk_kernel(
    const float* __restrict__ WfQ, const float* __restrict__ WfK, const float* __restrict__ WfV,
    const float* __restrict__ WQr, const float* __restrict__ WKr, const float* __restrict__ WVr,
    float* __restrict__ Wpart)
{
    const int z = blockIdx.z;
    const int mat = z >> 2;
    const int kq  = z & 3;
    const float* A = (mat == 0) ? WfQ : (mat == 1) ? WfK : WfV;
    const float* W = (mat == 0) ? WQr : (mat == 1) ? WKr : WVr;
    float* C = Wpart + (size_t)kq * DD * 3 * DD + mat * DD;
    const int ldc = 3 * DD;
    const int kbase = kq * 128;

    __shared__ uint32_t As[128 * GS_A];
    __shared__ uint32_t Bs[16 * GS_B];

    const int tid  = threadIdx.x;
    const int warp = tid >> 5;
    const int lane = tid & 31;
    const int qr   = lane >> 2;
    const int qc   = lane & 3;
    const int wm   = warp & 1;
    const int wn   = warp >> 1;
    const int m0   = blockIdx.y * 128;
    const int n0   = blockIdx.x * 128;

    float acc[4][4][4];
#pragma unroll
    for (int i = 0; i < 4; i++)
#pragma unroll
        for (int j = 0; j < 4; j++)
#pragma unroll
            for (int c = 0; c < 4; c++) acc[i][j][c] = 0.f;

    float4 ar[2], br[2];
#pragma unroll
    for (int p = 0; p < 2; p++) {
        int idx = p * 256 + tid;
        int arow = idx >> 2, ac = (idx & 3) * 4;
        ar[p] = *(const float4*)&A[(size_t)(m0 + arow) * DD + kbase + ac];
        int krow = idx >> 5, nc = (idx & 31) * 4;
        br[p] = *(const float4*)&W[(size_t)(kbase + krow) * DD + n0 + nc];
    }

    for (int k0 = 0; k0 < 128; k0 += 16) {
        __syncthreads();
#pragma unroll
        for (int p = 0; p < 2; p++) {
            int idx = p * 256 + tid;
            int arow = idx >> 2, ac = (idx & 3) * 4;
            As[arow * GS_A + ac + 0] = f2tf(ar[p].x);
            As[arow * GS_A + ac + 1] = f2tf(ar[p].y);
            As[arow * GS_A + ac + 2] = f2tf(ar[p].z);
            As[arow * GS_A + ac + 3] = f2tf(ar[p].w);
            int krow = idx >> 5, nc = (idx & 31) * 4;
            Bs[krow * GS_B + nc + 0] = f2tf(br[p].x);
            Bs[krow * GS_B + nc + 1] = f2tf(br[p].y);
            Bs[krow * GS_B + nc + 2] = f2tf(br[p].z);
            Bs[krow * GS_B + nc + 3] = f2tf(br[p].w);
        }
        __syncthreads();

        if (k0 + 16 < 128) {
#pragma unroll
            for (int p = 0; p < 2; p++) {
                int idx = p * 256 + tid;
                int arow = idx >> 2, ac = (idx & 3) * 4;
                ar[p] = *(const float4*)&A[(size_t)(m0 + arow) * DD + kbase + k0 + 16 + ac];
                int krow = idx >> 5, nc = (idx & 31) * 4;
                br[p] = *(const float4*)&W[(size_t)(kbase + k0 + 16 + krow) * DD + n0 + nc];
            }
        }

#pragma unroll
        for (int kk = 0; kk < 16; kk += 8) {
            uint32_t af[4][4], bf[4][2];
#pragma unroll
            for (int mt = 0; mt < 4; mt++) {
                int mrow = wm * 64 + mt * 16 + qr;
                af[mt][0] = As[mrow * GS_A + kk + qc];
                af[mt][1] = As[(mrow + 8) * GS_A + kk + qc];
                af[mt][2] = As[mrow * GS_A + kk + qc + 4];
                af[mt][3] = As[(mrow + 8) * GS_A + kk + qc + 4];
            }
#pragma unroll
            for (int nt = 0; nt < 4; nt++) {
                int ncol = wn * 32 + nt * 8 + qr;
                bf[nt][0] = Bs[(kk + qc) * GS_B + ncol];
                bf[nt][1] = Bs[(kk + qc + 4) * GS_B + ncol];
            }
#pragma unroll
            for (int mt = 0; mt < 4; mt++)
#pragma unroll
                for (int nt = 0; nt < 4; nt++)
                    MMA_TF32(acc[mt][nt], af[mt][0], af[mt][1], af[mt][2], af[mt][3],
                             bf[nt][0], bf[nt][1]);
        }
    }

#pragma unroll
    for (int mt = 0; mt < 4; mt++) {
        int row = m0 + wm * 64 + mt * 16 + qr;
#pragma unroll
        for (int nt = 0; nt < 4; nt++) {
            int col = n0 + wn * 32 + nt * 8 + qc * 2;
            float2 v0, v1;
            v0.x = acc[mt][nt][0]; v0.y = acc[mt][nt][1];
            v1.x = acc[mt][nt][2]; v1.y = acc[mt][nt][3];
            *(float2*)&C[(size_t)row * ldc + col] = v0;
            *(float2*)&C[(size_t)(row + 8) * ldc + col] = v1;
        }
    }
}

// ---------------- merge split-K partials -> tf32 Wqkv -----------------------
__global__ void compose_merge_kernel(const float* __restrict__ Wpart,
                                     float* __restrict__ Wqkv)
{
    const int n = DD * 3 * DD;
    int i = blockIdx.x * blockDim.x + threadIdx.x;
    if (i >= n) return;
    float s = Wpart[i] + Wpart[i + n] + Wpart[i + 2 * n] + Wpart[i + 3 * n];
    Wqkv[i] = __uint_as_float(f2tf(s));
}

// ---------------- flash attention: split-KV x4, no-max softmax --------------
// grid (8, 32, 4): z = KV quarter. Writes unnormalized fp32 partial O and
// per-row partial l; merge kernel normalizes.
#define AKS 68
#define AVS 72
#define APS 68
#define QROWS 256
#define KVSPLIT 4
#define KVLEN (SS/KVSPLIT)    // 512
#define ATT_SMEM ((64*AKS + 64*AVS + QROWS*APS) * (int)sizeof(uint32_t))

__global__ __launch_bounds__(256, 1) void attention_kernel(
    const float* __restrict__ Qh, const float* __restrict__ Kh,
    const float* __restrict__ Vh, int ld,
    float* __restrict__ Opart, float* __restrict__ Lpart)
{
    extern __shared__ uint32_t sm[];
    uint32_t* Ks = sm;
    uint32_t* Vs = Ks + 64 * AKS;
    uint32_t* Ps = Vs + 64 * AVS;

    const int tid  = threadIdx.x;
    const int w    = tid >> 5;
    const int lane = tid & 31;
    const int qr   = lane >> 2;
    const int qc   = lane & 3;
    const int q0   = blockIdx.x * QROWS;
    const int bh   = blockIdx.y;
    const int kvq  = blockIdx.z;
    const int rb   = (bh >> 3) * SS;
    const int cq   = (bh & 7) * DHEAD;
    const int kv0  = kvq * KVLEN;

#pragma unroll
    for (int p = 0; p < 16; ++p) {
        int idx = p * 256 + tid;
        int r = idx >> 4, kc = (idx & 15) * 4;
        uint4 u = *(const uint4*)&Qh[(size_t)(rb + q0 + r) * ld + cq + kc];
        *(uint4*)&Ps[r * APS + kc] = u;
    }
    __syncthreads();

    uint32_t qf[2][8][4];
#pragma unroll
    for (int mt = 0; mt < 2; mt++) {
        int base0 = (w * 32 + mt * 16 + qr) * APS;
        int base1 = (w * 32 + mt * 16 + qr + 8) * APS;
#pragma unroll
        for (int ks = 0; ks < 8; ks++) {
            int kk = ks * 8;
            qf[mt][ks][0] = Ps[base0 + kk + qc];
            qf[mt][ks][1] = Ps[base1 + kk + qc];
            qf[mt][ks][2] = Ps[base0 + kk + qc + 4];
            qf[mt][ks][3] = Ps[base1 + kk + qc + 4];
        }
    }

    float l[2][2];
    float o[2][8][4];
#pragma unroll
    for (int mt = 0; mt < 2; mt++) {
        l[mt][0] = 0.f; l[mt][1] = 0.f;
#pragma unroll
        for (int i = 0; i < 8; i++)
#pragma unroll
            for (int c = 0; c < 4; c++) o[mt][i][c] = 0.f;
    }

    for (int s0 = kv0; s0 < kv0 + KVLEN; s0 += 64) {
        __syncthreads();
#pragma unroll
        for (int p = 0; p < 4; p++) {
            int idx = p * 256 + tid;
            int r = idx >> 4, kc = (idx & 15) * 4;
            uint4 uk = *(const uint4*)&Kh[(size_t)(rb + s0 + r) * ld + cq + kc];
            uint4 uv = *(const uint4*)&Vh[(size_t)(rb + s0 + r) * ld + cq + kc];
            *(uint4*)&Ks[r * AKS + kc] = uk;
            *(uint4*)&Vs[r * AVS + kc] = uv;
        }
        __syncthreads();

        float s[2][8][4];
#pragma unroll
        for (int mt = 0; mt < 2; mt++)
#pragma unroll
            for (int nt = 0; nt < 8; nt++)
#pragma unroll
                for (int c = 0; c < 4; c++) s[mt][nt][c] = 0.f;

#pragma unroll
        for (int ks = 0; ks < 8; ks++) {
            int kk = ks * 8;
#pragma unroll
            for (int nt = 0; nt < 8; nt++) {
                uint32_t b0 = Ks[(nt * 8 + qr) * AKS + kk + qc];
                uint32_t b1 = Ks[(nt * 8 + qr) * AKS + kk + qc + 4];
                MMA_TF32(s[0][nt], qf[0][ks][0], qf[0][ks][1], qf[0][ks][2], qf[0][ks][3], b0, b1);
                MMA_TF32(s[1][nt], qf[1][ks][0], qf[1][ks][1], qf[1][ks][2], qf[1][ks][3], b0, b1);
            }
        }

        // no-max softmax
#pragma unroll
        for (int mt = 0; mt < 2; mt++) {
            int prow0 = (w * 32 + mt * 16 + qr) * APS;
            int prow1 = (w * 32 + mt * 16 + qr + 8) * APS;
            float rs0 = 0.f, rs1 = 0.f;
#pragma unroll
            for (int nt = 0; nt < 8; nt++) {
                float p0 = ex2(s[mt][nt][0]);
                float p1 = ex2(s[mt][nt][1]);
                float p2 = ex2(s[mt][nt][2]);
                float p3 = ex2(s[mt][nt][3]);
                rs0 += p0 + p1;
                rs1 += p2 + p3;
                int col = nt * 8 + 2 * qc;
                Ps[prow0 + col]     = f2tf(p0);
                Ps[prow0 + col + 1] = f2tf(p1);
                Ps[prow1 + col]     = f2tf(p2);
                Ps[prow1 + col + 1] = f2tf(p3);
            }
            l[mt][0] += rs0;
            l[mt][1] += rs1;
        }
        __syncwarp();

        // O += P V
#pragma unroll
        for (int ks = 0; ks < 8; ks++) {
            int kk = ks * 8;
            uint32_t b[8][2];
#pragma unroll
            for (int vt = 0; vt < 8; vt++) {
                b[vt][0] = Vs[(kk + qc) * AVS + vt * 8 + qr];
                b[vt][1] = Vs[(kk + qc + 4) * AVS + vt * 8 + qr];
            }
#pragma unroll
            for (int mt = 0; mt < 2; mt++) {
                int prow0 = (w * 32 + mt * 16 + qr) * APS;
                int prow1 = (w * 32 + mt * 16 + qr + 8) * APS;
                uint32_t a0 = Ps[prow0 + kk + qc];
                uint32_t a1 = Ps[prow1 + kk + qc];
                uint32_t a2 = Ps[prow0 + kk + qc + 4];
                uint32_t a3 = Ps[prow1 + kk + qc + 4];
#pragma unroll
                for (int vt = 0; vt < 8; vt++)
                    MMA_TF32(o[mt][vt], a0, a1, a2, a3, b[vt][0], b[vt][1]);
            }
        }
    }

    // epilogue: write unnormalized partial O (fp32) and partial l
    float* Op = Opart + (size_t)kvq * NT;
#pragma unroll
    for (int mt = 0; mt < 2; mt++) {
        float l0 = l[mt][0], l1 = l[mt][1];
        l0 += __shfl_xor_sync(0xffffffffu, l0, 1);
        l0 += __shfl_xor_sync(0xffffffffu, l0, 2);
        l1 += __shfl_xor_sync(0xffffffffu, l1, 1);
        l1 += __shfl_xor_sync(0xffffffffu, l1, 2);
        int row = rb + q0 + w * 32 + mt * 16 + qr;
        if (qc == 0) {
            Lpart[((size_t)kvq * NTOK + row) * HH + (bh & 7)]     = l0;
            Lpart[((size_t)kvq * NTOK + row + 8) * HH + (bh & 7)] = l1;
        }
#pragma unroll
        for (int vt = 0; vt < 8; vt++) {
            int col = cq + vt * 8 + 2 * qc;
            float2 v0, v1;
            v0.x = o[mt][vt][0]; v0.y = o[mt][vt][1];
            v1.x = o[mt][vt][2]; v1.y = o[mt][vt][3];
            *(float2*)&Op[(size_t)row * DD + col] = v0;
            *(float2*)&Op[(size_t)(row + 8) * DD + col] = v1;
        }
    }
}

// ---------------- merge split-KV partials -> normalized tf32 ATT ------------
__global__ void attn_merge_kernel(const float* __restrict__ Opart,
                                  const float* __restrict__ Lpart,
                                  float* __restrict__ ATT)
{
    int i4 = blockIdx.x * blockDim.x + threadIdx.x;   // over NT/4
    if (i4 >= NT / 4) return;
    size_t base = (size_t)i4 * 4;
    int row = (int)(base >> 9);
    int col = (int)(base & (DD - 1));
    int h = col >> 6;

    float l = Lpart[(size_t)row * HH + h]
            + Lpart[((size_t)NTOK + row) * HH + h]
            + Lpart[((size_t)2 * NTOK + row) * HH + h]
            + Lpart[((size_t)3 * NTOK + row) * HH + h];
    float inv = 1.f / l;

    float4 a = *(const float4*)&Opart[base];
    float4 b = *(const float4*)&Opart[base + NT];
    float4 c = *(const float4*)&Opart[base + 2 * (size_t)NT];
    float4 d = *(const float4*)&Opart[base + 3 * (size_t)NT];
    float4 r;
    r.x = __uint_as_float(f2tf((a.x + b.x + c.x + d.x) * inv));
    r.y = __uint_as_float(f2tf((a.y + b.y + c.y + d.y) * inv));
    r.z = __uint_as_float(f2tf((a.z + b.z + c.z + d.z) * inv));
    r.w = __uint_as_float(f2tf((a.w + b.w + c.w + d.w) * inv));
    *(float4*)&ATT[base] = r;
}

// ---------------- fused residual + LayerNorm (+relu / tf32-out) -------------
__global__ __launch_bounds__(128) void add_ln_kernel(
    const float* __restrict__ X, const float* __restrict__ R,
    const float* __restrict__ gamma, const float* __restrict__ beta,
    float* __restrict__ out, int relu, int tf32_out)
{
    const int row = blockIdx.x;
    const int tid = threadIdx.x;

    float4 xv = *(const float4*)&X[(size_t)row * DD + tid * 4];
    float4 rv = *(const float4*)&R[(size_t)row * DD + tid * 4];
    float v[4] = { xv.x + rv.x, xv.y + rv.y, xv.z + rv.z, xv.w + rv.w };

    float s = v[0] + v[1] + v[2] + v[3];
    float sq = v[0] * v[0] + v[1] * v[1] + v[2] * v[2] + v[3] * v[3];
#pragma unroll
    for (int off = 16; off >= 1; off >>= 1) {
        s += __shfl_xor_sync(0xffffffffu, s, off);
        sq += __shfl_xor_sync(0xffffffffu, sq, off);
    }
    __shared__ float sw[4], sqw[4];
    int w = tid >> 5;
    if ((tid & 31) == 0) { sw[w] = s; sqw[w] = sq; }
    __syncthreads();
    s = sw[0] + sw[1] + sw[2] + sw[3];
    sq = sqw[0] + sqw[1] + sqw[2] + sqw[3];

    float mean = s * (1.0f / (float)DD);
    float var = sq * (1.0f / (float)DD) - mean * mean;
    float rstd = rsqrtf(var + 1e-5f);

    float4 gv = *(const float4*)&gamma[tid * 4];
    float4 bv = *(const float4*)&beta[tid * 4];
    float ga[4] = { gv.x, gv.y, gv.z, gv.w };
    float be[4] = { bv.x, bv.y, bv.z, bv.w };

    float ov[4];
#pragma unroll
    for (int j = 0; j < 4; j++) {
        float t = (v[j] - mean) * rstd * ga[j] + be[j];
        if (relu) t = fmaxf(t, 0.f);
        if (tf32_out) t = __uint_as_float(f2tf(t));
        ov[j] = t;
    }
    *(float4*)&out[(size_t)row * DD + tid * 4] = *(float4*)ov;
}

// ---------------- launch ------------------------------------------------------
extern "C" void kernel_launch(void* const* d_in, const int* in_sizes, int n_in,
                              void* d_out, int out_size)
{
    (void)in_sizes; (void)n_in; (void)out_size;

    const int*   x    = (const int*)  d_in[0];
    const float* emb  = (const float*)d_in[1];
    const float* WfQ  = (const float*)d_in[2];
    const float* bfQ  = (const float*)d_in[3];
    const float* WfK  = (const float*)d_in[4];
    const float* bfK  = (const float*)d_in[5];
    const float* WfV  = (const float*)d_in[6];
    const float* bfV  = (const float*)d_in[7];
    const float* WQ   = (const float*)d_in[8];
    const float* bQ   = (const float*)d_in[9];
    const float* WK   = (const float*)d_in[10];
    const float* bK   = (const float*)d_in[11];
    const float* WV   = (const float*)d_in[12];
    const float* bV   = (const float*)d_in[13];
    const float* Wo   = (const float*)d_in[14];
    const float* bo   = (const float*)d_in[15];
    const float* W1   = (const float*)d_in[16];
    const float* b1   = (const float*)d_in[17];
    const float* W2   = (const float*)d_in[18];
    const float* b2   = (const float*)d_in[19];
    const float* gamma= (const float*)d_in[20];
    const float* beta = (const float*)d_in[21];
    float* out = (float*)d_out;

    float* base = nullptr;
    cudaGetSymbolAddress((void**)&base, g_scratch);

    float* Z    = base + 0 * (size_t)NT;
    float* QKVH = base + 1 * (size_t)NT;     // 8192 x 1536 (tf32 bits)
    float* ATT  = base + 4 * (size_t)NT;     // tf32 bits
    float* AO   = base + 5 * (size_t)NT;     // fp32
    float* Aa   = base + 6 * (size_t)NT;     // tf32 bits
    float* H1   = base + 7 * (size_t)NT;     // FFN intermediate; reused as Opart
    float* F    = base + 11 * (size_t)NT;    // fp32
    float* WQr  = base + 12 * (size_t)NT;    // tf32
    float* WKr  = WQr + DD * DD;
    float* WVr  = WKr + DD * DD;
    float* Wqkv = WVr + DD * DD;             // 512 x 1536 tf32
    float* bqkv = Wqkv + 3 * DD * DD;        // 1536 fp32
    float* Wpart= bqkv + 2048;               // compose partials; reused as Lpart

    float* Opart = H1;                        // 4 x NT fp32 (consumed before FFN)
    float* Lpart = Wpart;                     // 4 x NTOK x HH fp32 (compose done)

    cudaFuncSetAttribute(attention_kernel,
                         cudaFuncAttributeMaxDynamicSharedMemorySize, ATT_SMEM);

    // 1. embedding + inline PE, batch-amortized (tf32 out)
    embed_pe_kernel<<<SS * DD / 256, 256>>>(x, emb, Z);

    // 2. merged repack of per-head weights -> tf32
    repack3_kernel<<<3 * DD * DD / 256, 256>>>(WQ, WK, WV, WQr, WKr, WVr);

    // 3. merged bias compose
    bias_compose3_kernel<<<6, 256>>>(bfQ, bfK, bfV, WQr, WKr, WVr, bQ, bK, bV, bqkv);

    // 4. split-K batched weight composition + merge
    gemm_compose_splitk_kernel<<<dim3(DD / 128, DD / 128, 12), 256>>>(
        WfQ, WfK, WfV, WQr, WKr, WVr, Wpart);
    compose_merge_kernel<<<(3 * DD * DD + 255) / 256, 256>>>(Wpart, Wqkv);

    // 5. fused QKV head projection -> tf32 bits, Q pre-scaled
    dim3 gqkv(3 * DD / 128, NTOK / 128);
    gemm_tf32_kernel<<<gqkv, 256>>>(NTOK, 3 * DD, DD, 3 * DD, Z, Wqkv, bqkv, QKVH, 2);

    // 6. attention split-KV x4 (1024 CTAs) + merge
    attention_kernel<<<dim3(SS / QROWS, BB * HH, KVSPLIT), 256, ATT_SMEM>>>(
        QKVH, QKVH + DD, QKVH + 2 * DD, 3 * DD, Opart, Lpart);
    attn_merge_kernel<<<NT / 4 / 256, 256>>>(Opart, Lpart, ATT);

    // 7. output projection (fp32 out) + residual LN (tf32 out)
    dim3 g512(DD / 128, NTOK / 128);
    gemm_tf32_kernel<<<g512, 256>>>(NTOK, DD, DD, DD, ATT, Wo, bo, AO, 0);
    add_ln_kernel<<<NTOK, 128>>>(AO, Z, gamma, beta, Aa, 0, 1);

    // 8. FFN (H1 region now free; FFN1 overwrites Opart)
    dim3 gff(DFF / 128, NTOK / 128);
    gemm_tf32_kernel<<<gff, 256>>>(NTOK, DFF, DD, DFF, Aa, W1, b1, H1, 1);
    gemm_tf32_kernel<<<g512, 256>>>(NTOK, DD, DFF, DD, H1, W2, b2, F, 0);

    // 9. residual LN + final relu -> fp32 output
    add_ln_kernel<<<NTOK, 128>>>(F, Aa, gamma, beta, out, 1, 0);
}

// round 16
// speedup vs baseline: 1.0213x; 1.0213x over previous
#include <cuda_runtime.h>
#include <math.h>
#include <stdint.h>

// ---------------- problem constants ----------------
#define BB 4
#define SS 2048
#define DD 512
#define HH 8
#define DHEAD 64
#define DFF 2048
#define NTOK (BB*SS)          // 8192 tokens
#define NT (NTOK*DD)          // 4194304 floats per [tokens, 512] buffer

// ---------------- scratch ----------------
__device__ float g_scratch[12*(size_t)NT + 6*DD*DD + 2048 + 12*DD*DD];

// ---------------- helpers ----------------
__device__ __forceinline__ uint32_t f2tf(float x) {
    uint32_t u;
    asm("cvt.rna.tf32.f32 %0, %1;" : "=r"(u) : "f"(x));
    return u;
}

__device__ __forceinline__ float ex2(float x) {
    float y;
    asm("ex2.approx.f32 %0, %1;" : "=f"(y) : "f"(x));
    return y;
}

#define MMA_TF32(d, a0, a1, a2, a3, b0, b1)                                \
    asm volatile("mma.sync.aligned.m16n8k8.row.col.f32.tf32.tf32.f32 "     \
        "{%0,%1,%2,%3}, {%4,%5,%6,%7}, {%8,%9}, {%0,%1,%2,%3};"            \
        : "+f"(d[0]), "+f"(d[1]), "+f"(d[2]), "+f"(d[3])                   \
        : "r"(a0), "r"(a1), "r"(a2), "r"(a3), "r"(b0), "r"(b1))

// scale folded into Q at GEMM epilogue: 1/sqrt(64) * log2(e)
#define QSCALE 0.180336880f

// ---------------- merged prep: embed+PE | repack3 | bias-compose ------------
// blocks [0, 4096): embed over SS*DD (batch-amortized)
// blocks [4096, 7168): repack 3 per-head weights -> tf32
// blocks [7168, 7174): composed bias (reads raw W with repack indexing)
#define PREP_EMBED_BLOCKS (SS * DD / 256)          // 4096
#define PREP_REPACK_BLOCKS (3 * DD * DD / 256)     // 3072
#define PREP_BIAS_BLOCKS 6
#define PREP_BLOCKS (PREP_EMBED_BLOCKS + PREP_REPACK_BLOCKS + PREP_BIAS_BLOCKS)

__global__ void prep_kernel(
    const int* __restrict__ x, const float* __restrict__ emb,
    const float* __restrict__ WQ, const float* __restrict__ WK, const float* __restrict__ WV,
    const float* __restrict__ bfQ, const float* __restrict__ bfK, const float* __restrict__ bfV,
    const float* __restrict__ bQ,  const float* __restrict__ bK,  const float* __restrict__ bV,
    float* __restrict__ z,
    float* __restrict__ WQr, float* __restrict__ WKr, float* __restrict__ WVr,
    float* __restrict__ bqkv)
{
    int blk = blockIdx.x;
    if (blk < PREP_EMBED_BLOCKS) {
        int idx = blk * 256 + threadIdx.x;           // over SS*DD
        int d = idx & (DD - 1);
        int s = idx >> 9;
        float di = (float)d * (1.0f / (float)DD);
        float ang = (float)s / powf(10000.0f, di);
        float pe = (d & 1) ? cosf(ang) : sinf(ang);
#pragma unroll
        for (int b = 0; b < BB; b++) {
            int t = b * SS + s;
            z[(size_t)t * DD + d] = __uint_as_float(f2tf(emb[(size_t)x[t] * DD + d] + pe));
        }
    } else if (blk < PREP_EMBED_BLOCKS + PREP_REPACK_BLOCKS) {
        int gidx = (blk - PREP_EMBED_BLOCKS) * 256 + threadIdx.x;
        int which = gidx / (DD * DD);
        int idx = gidx - which * (DD * DD);
        const float* W = (which == 0) ? WQ : (which == 1) ? WK : WV;
        float* Wr = (which == 0) ? WQr : (which == 1) ? WKr : WVr;
        int n = idx & (DD - 1);
        int d = idx >> 9;
        int h = n >> 6, k = n & 63;
        Wr[idx] = __uint_as_float(f2tf(W[((size_t)h * DD + d) * DHEAD + k]));
    } else {
        int g = (blk - PREP_EMBED_BLOCKS - PREP_REPACK_BLOCKS) * 256 + threadIdx.x;
        if (g >= 3 * DD) return;
        int which = g >> 9;
        int n = g & (DD - 1);
        const float* bf = (which == 0) ? bfQ : (which == 1) ? bfK : bfV;
        const float* W  = (which == 0) ? WQ : (which == 1) ? WK : WV;
        const float* bh = (which == 0) ? bQ : (which == 1) ? bK : bV;
        int h = n >> 6, kk = n & 63;
        float s = bh[n];
        for (int k = 0; k < DD; k++)
            s += bf[k] * __uint_as_float(f2tf(W[((size_t)h * DD + k) * DHEAD + kk]));
        bqkv[g] = s;
    }
}

// ---------------- tf32 tensor-core GEMM (cvt-in-staging) --------------------
#define GS_A 20
#define GS_B 136

__global__ __launch_bounds__(256, 2) void gemm_tf32_kernel(
    int M, int N, int K, int ldc,
    const float* __restrict__ A, const float* __restrict__ W,
    const float* __restrict__ bias, float* __restrict__ C, int mode)
{
    __shared__ uint32_t As[128 * GS_A];
    __shared__ uint32_t Bs[16 * GS_B];

    const int tid  = threadIdx.x;
    const int warp = tid >> 5;
    const int lane = tid & 31;
    const int qr   = lane >> 2;
    const int qc   = lane & 3;
    const int wm   = warp & 1;
    const int wn   = warp >> 1;
    const int m0   = blockIdx.y * 128;
    const int n0   = blockIdx.x * 128;

    float acc[4][4][4];
#pragma unroll
    for (int i = 0; i < 4; i++)
#pragma unroll
        for (int j = 0; j < 4; j++)
#pragma unroll
            for (int c = 0; c < 4; c++) acc[i][j][c] = 0.f;

    float4 ar[2], br[2];
#pragma unroll
    for (int p = 0; p < 2; p++) {
        int idx = p * 256 + tid;
        int arow = idx >> 2, ac = (idx & 3) * 4;
        ar[p] = *(const float4*)&A[(size_t)(m0 + arow) * K + ac];
        int krow = idx >> 5, nc = (idx & 31) * 4;
        br[p] = *(const float4*)&W[(size_t)krow * N + n0 + nc];
    }

    for (int k0 = 0; k0 < K; k0 += 16) {
        __syncthreads();
#pragma unroll
        for (int p = 0; p < 2; p++) {
            int idx = p * 256 + tid;
            int arow = idx >> 2, ac = (idx & 3) * 4;
            As[arow * GS_A + ac + 0] = f2tf(ar[p].x);
            As[arow * GS_A + ac + 1] = f2tf(ar[p].y);
            As[arow * GS_A + ac + 2] = f2tf(ar[p].z);
            As[arow * GS_A + ac + 3] = f2tf(ar[p].w);
            int krow = idx >> 5, nc = (idx & 31) * 4;
            Bs[krow * GS_B + nc + 0] = f2tf(br[p].x);
            Bs[krow * GS_B + nc + 1] = f2tf(br[p].y);
            Bs[krow * GS_B + nc + 2] = f2tf(br[p].z);
            Bs[krow * GS_B + nc + 3] = f2tf(br[p].w);
        }
        __syncthreads();

        if (k0 + 16 < K) {
#pragma unroll
            for (int p = 0; p < 2; p++) {
                int idx = p * 256 + tid;
                int arow = idx >> 2, ac = (idx & 3) * 4;
                ar[p] = *(const float4*)&A[(size_t)(m0 + arow) * K + k0 + 16 + ac];
                int krow = idx >> 5, nc = (idx & 31) * 4;
                br[p] = *(const float4*)&W[(size_t)(k0 + 16 + krow) * N + n0 + nc];
            }
        }

#pragma unroll
        for (int kk = 0; kk < 16; kk += 8) {
            uint32_t af[4][4], bf[4][2];
#pragma unroll
            for (int mt = 0; mt < 4; mt++) {
                int mrow = wm * 64 + mt * 16 + qr;
                af[mt][0] = As[mrow * GS_A + kk + qc];
                af[mt][1] = As[(mrow + 8) * GS_A + kk + qc];
                af[mt][2] = As[mrow * GS_A + kk + qc + 4];
                af[mt][3] = As[(mrow + 8) * GS_A + kk + qc + 4];
            }
#pragma unroll
            for (int nt = 0; nt < 4; nt++) {
                int ncol = wn * 32 + nt * 8 + qr;
                bf[nt][0] = Bs[(kk + qc) * GS_B + ncol];
                bf[nt][1] = Bs[(kk + qc + 4) * GS_B + ncol];
            }
#pragma unroll
            for (int mt = 0; mt < 4; mt++)
#pragma unroll
                for (int nt = 0; nt < 4; nt++)
                    MMA_TF32(acc[mt][nt], af[mt][0], af[mt][1], af[mt][2], af[mt][3],
                             bf[nt][0], bf[nt][1]);
        }
    }

    // epilogue
#pragma unroll
    for (int mt = 0; mt < 4; mt++) {
        int row = m0 + wm * 64 + mt * 16 + qr;
#pragma unroll
        for (int nt = 0; nt < 4; nt++) {
            int col = n0 + wn * 32 + nt * 8 + qc * 2;
            float2 bv = bias ? *(const float2*)&bias[col] : make_float2(0.f, 0.f);
            float2 v0, v1;
            v0.x = acc[mt][nt][0] + bv.x;
            v0.y = acc[mt][nt][1] + bv.y;
            v1.x = acc[mt][nt][2] + bv.x;
            v1.y = acc[mt][nt][3] + bv.y;
            if (mode == 1) {
                v0.x = __uint_as_float(f2tf(fmaxf(v0.x, 0.f)));
                v0.y = __uint_as_float(f2tf(fmaxf(v0.y, 0.f)));
                v1.x = __uint_as_float(f2tf(fmaxf(v1.x, 0.f)));
                v1.y = __uint_as_float(f2tf(fmaxf(v1.y, 0.f)));
            } else if (mode == 2) {
                float sc = (col < DD) ? QSCALE : 1.0f;
                v0.x = __uint_as_float(f2tf(v0.x * sc));
                v0.y = __uint_as_float(f2tf(v0.y * sc));
                v1.x = __uint_as_float(f2tf(v1.x * sc));
                v1.y = __uint_as_float(f2tf(v1.y * sc));
            } else if (mode == 3) {
                v0.x = __uint_as_float(f2tf(v0.x));
                v0.y = __uint_as_float(f2tf(v0.y));
                v1.x = __uint_as_float(f2tf(v1.x));
                v1.y = __uint_as_float(f2tf(v1.y));
            }
            *(float2*)&C[(size_t)row * ldc + col] = v0;
            *(float2*)&C[(size_t)(row + 8) * ldc + col] = v1;
        }
    }
}

// ---------------- split-K compose GEMM ------------------------
__global__ __launch_bounds__(256, 2) void gemm_compose_splitk_kernel(
    const float* __restrict__ WfQ, const float* __restrict__ WfK, const float* __restrict__ WfV,
    const float* __restrict__ WQr, const float* __restrict__ WKr, const float* __restrict__ WVr,
    float* __restrict__ Wpart)
{
    const int z = blockIdx.z;
    const int mat = z >> 2;
    const int kq  = z & 3;
    const float* A = (mat == 0) ? WfQ : (mat == 1) ? WfK : WfV;
    const float* W = (mat == 0) ? WQr : (mat == 1) ? WKr : WVr;
    float* C = Wpart + (size_t)kq * DD * 3 * DD + mat * DD;
    const int ldc = 3 * DD;
    const int kbase = kq * 128;

    __shared__ uint32_t As[128 * GS_A];
    __shared__ uint32_t Bs[16 * GS_B];

    const int tid  = threadIdx.x;
    const int warp = tid >> 5;
    const int lane = tid & 31;
    const int qr   = lane >> 2;
    const int qc   = lane & 3;
    const int wm   = warp & 1;
    const int wn   = warp >> 1;
    const int m0   = blockIdx.y * 128;
    const int n0   = blockIdx.x * 128;

    float acc[4][4][4];
#pragma unroll
    for (int i = 0; i < 4; i++)
#pragma unroll
        for (int j = 0; j < 4; j++)
#pragma unroll
            for (int c = 0; c < 4; c++) acc[i][j][c] = 0.f;

    float4 ar[2], br[2];
#pragma unroll
    for (int p = 0; p < 2; p++) {
        int idx = p * 256 + tid;
        int arow = idx >> 2, ac = (idx & 3) * 4;
        ar[p] = *(const float4*)&A[(size_t)(m0 + arow) * DD + kbase + ac];
        int krow = idx >> 5, nc = (idx & 31) * 4;
        br[p] = *(const float4*)&W[(size_t)(kbase + krow) * DD + n0 + nc];
    }

    for (int k0 = 0; k0 < 128; k0 += 16) {
        __syncthreads();
#pragma unroll
        for (int p = 0; p < 2; p++) {
            int idx = p * 256 + tid;
            int arow = idx >> 2, ac = (idx & 3) * 4;
            As[arow * GS_A + ac + 0] = f2tf(ar[p].x);
            As[arow * GS_A + ac + 1] = f2tf(ar[p].y);
            As[arow * GS_A + ac + 2] = f2tf(ar[p].z);
            As[arow * GS_A + ac + 3] = f2tf(ar[p].w);
            int krow = idx >> 5, nc = (idx & 31) * 4;
            Bs[krow * GS_B + nc + 0] = f2tf(br[p].x);
            Bs[krow * GS_B + nc + 1] = f2tf(br[p].y);
            Bs[krow * GS_B + nc + 2] = f2tf(br[p].z);
            Bs[krow * GS_B + nc + 3] = f2tf(br[p].w);
        }
        __syncthreads();

        if (k0 + 16 < 128) {
#pragma unroll
            for (int p = 0; p < 2; p++) {
                int idx = p * 256 + tid;
                int arow = idx >> 2, ac = (idx & 3) * 4;
                ar[p] = *(const float4*)&A[(size_t)(m0 + arow) * DD + kbase + k0 + 16 + ac];
                int krow = idx >> 5, nc = (idx & 31) * 4;
                br[p] = *(const float4*)&W[(size_t)(kbase + k0 + 16 + krow) * DD + n0 + nc];
            }
        }

#pragma unroll
        for (int kk = 0; kk < 16; kk += 8) {
            uint32_t af[4][4], bf[4][2];
#pragma unroll
            for (int mt = 0; mt < 4; mt++) {
                int mrow = wm * 64 + mt * 16 + qr;
                af[mt][0] = As[mrow * GS_A + kk + qc];
                af[mt][1] = As[(mrow + 8) * GS_A + kk + qc];
                af[mt][2] = As[mrow * GS_A + kk + qc + 4];
                af[mt][3] = As[(mrow + 8) * GS_A + kk + qc + 4];
            }
#pragma unroll
            for (int nt = 0; nt < 4; nt++) {
                int ncol = wn * 32 + nt * 8 + qr;
                bf[nt][0] = Bs[(kk + qc) * GS_B + ncol];
                bf[nt][1] = Bs[(kk + qc + 4) * GS_B + ncol];
            }
#pragma unroll
            for (int mt = 0; mt < 4; mt++)
#pragma unroll
                for (int nt = 0; nt < 4; nt++)
                    MMA_TF32(acc[mt][nt], af[mt][0], af[mt][1], af[mt][2], af[mt][3],
                             bf[nt][0], bf[nt][1]);
        }
    }

#pragma unroll
    for (int mt = 0; mt < 4; mt++) {
        int row = m0 + wm * 64 + mt * 16 + qr;
#pragma unroll
        for (int nt = 0; nt < 4; nt++) {
            int col = n0 + wn * 32 + nt * 8 + qc * 2;
            float2 v0, v1;
            v0.x = acc[mt][nt][0]; v0.y = acc[mt][nt][1];
            v1.x = acc[mt][nt][2]; v1.y = acc[mt][nt][3];
            *(float2*)&C[(size_t)row * ldc + col] = v0;
            *(float2*)&C[(size_t)(row + 8) * ldc + col] = v1;
        }
    }
}

// ---------------- merge split-K partials -> tf32 Wqkv -----------------------
__global__ void compose_merge_kernel(const float* __restrict__ Wpart,
                                     float* __restrict__ Wqkv)
{
    const int n = DD * 3 * DD;
    int i = blockIdx.x * blockDim.x + threadIdx.x;
    if (i >= n) return;
    float s = Wpart[i] + Wpart[i + n] + Wpart[i + 2 * n] + Wpart[i + 3 * n];
    Wqkv[i] = __uint_as_float(f2tf(s));
}

// ---------------- flash attention: 128-row KV staging, no-max softmax -------
#define AKS 68
#define AVS 72
#define APS 68
#define QROWS 256
#define ATT_SMEM ((128*AKS + 128*AVS + QROWS*APS) * (int)sizeof(uint32_t))

__global__ __launch_bounds__(256, 1) void attention_kernel(
    const float* __restrict__ Qh, const float* __restrict__ Kh,
    const float* __restrict__ Vh, int ld, float* __restrict__ Out)
{
    extern __shared__ uint32_t sm[];
    uint32_t* Ks = sm;                      // 128 x AKS
    uint32_t* Vs = Ks + 128 * AKS;          // 128 x AVS
    uint32_t* Ps = Vs + 128 * AVS;          // QROWS x APS; also Q staging

    const int tid  = threadIdx.x;
    const int w    = tid >> 5;
    const int lane = tid & 31;
    const int qr   = lane >> 2;
    const int qc   = lane & 3;
    const int q0   = blockIdx.x * QROWS;
    const int bh   = blockIdx.y;
    const int rb   = (bh >> 3) * SS;
    const int cq   = (bh & 7) * DHEAD;

    // stage Q (tf32 + QSCALE): bit-copies
#pragma unroll
    for (int p = 0; p < 16; ++p) {
        int idx = p * 256 + tid;
        int r = idx >> 4, kc = (idx & 15) * 4;
        uint4 u = *(const uint4*)&Qh[(size_t)(rb + q0 + r) * ld + cq + kc];
        *(uint4*)&Ps[r * APS + kc] = u;
    }
    __syncthreads();

    uint32_t qf[2][8][4];
#pragma unroll
    for (int mt = 0; mt < 2; mt++) {
        int base0 = (w * 32 + mt * 16 + qr) * APS;
        int base1 = (w * 32 + mt * 16 + qr + 8) * APS;
#pragma unroll
        for (int ks = 0; ks < 8; ks++) {
            int kk = ks * 8;
            qf[mt][ks][0] = Ps[base0 + kk + qc];
            qf[mt][ks][1] = Ps[base1 + kk + qc];
            qf[mt][ks][2] = Ps[base0 + kk + qc + 4];
            qf[mt][ks][3] = Ps[base1 + kk + qc + 4];
        }
    }

    float l[2][2];
    float o[2][8][4];
#pragma unroll
    for (int mt = 0; mt < 2; mt++) {
        l[mt][0] = 0.f; l[mt][1] = 0.f;
#pragma unroll
        for (int i = 0; i < 8; i++)
#pragma unroll
            for (int c = 0; c < 4; c++) o[mt][i][c] = 0.f;
    }

    for (int s0 = 0; s0 < SS; s0 += 128) {
        __syncthreads();
        // stage 128 KV rows: 8 uint4 per thread per matrix
#pragma unroll
        for (int p = 0; p < 8; p++) {
            int idx = p * 256 + tid;
            int r = idx >> 4, kc = (idx & 15) * 4;
            uint4 uk = *(const uint4*)&Kh[(size_t)(rb + s0 + r) * ld + cq + kc];
            uint4 uv = *(const uint4*)&Vh[(size_t)(rb + s0 + r) * ld + cq + kc];
            *(uint4*)&Ks[r * AKS + kc] = uk;
            *(uint4*)&Vs[r * AVS + kc] = uv;
        }
        __syncthreads();

#pragma unroll
        for (int chunk = 0; chunk < 2; chunk++) {
            uint32_t* Kc = Ks + chunk * 64 * AKS;
            uint32_t* Vc = Vs + chunk * 64 * AVS;

            float s[2][8][4];
#pragma unroll
            for (int mt = 0; mt < 2; mt++)
#pragma unroll
                for (int nt = 0; nt < 8; nt++)
#pragma unroll
                    for (int c = 0; c < 4; c++) s[mt][nt][c] = 0.f;

#pragma unroll
            for (int ks = 0; ks < 8; ks++) {
                int kk = ks * 8;
#pragma unroll
                for (int nt = 0; nt < 8; nt++) {
                    uint32_t b0 = Kc[(nt * 8 + qr) * AKS + kk + qc];
                    uint32_t b1 = Kc[(nt * 8 + qr) * AKS + kk + qc + 4];
                    MMA_TF32(s[0][nt], qf[0][ks][0], qf[0][ks][1], qf[0][ks][2], qf[0][ks][3], b0, b1);
                    MMA_TF32(s[1][nt], qf[1][ks][0], qf[1][ks][1], qf[1][ks][2], qf[1][ks][3], b0, b1);
                }
            }

            // no-max softmax
#pragma unroll
            for (int mt = 0; mt < 2; mt++) {
                int prow0 = (w * 32 + mt * 16 + qr) * APS;
                int prow1 = (w * 32 + mt * 16 + qr + 8) * APS;
                float rs0 = 0.f, rs1 = 0.f;
#pragma unroll
                for (int nt = 0; nt < 8; nt++) {
                    float p0 = ex2(s[mt][nt][0]);
                    float p1 = ex2(s[mt][nt][1]);
                    float p2 = ex2(s[mt][nt][2]);
                    float p3 = ex2(s[mt][nt][3]);
                    rs0 += p0 + p1;
                    rs1 += p2 + p3;
                    int col = nt * 8 + 2 * qc;
                    Ps[prow0 + col]     = f2tf(p0);
                    Ps[prow0 + col + 1] = f2tf(p1);
                    Ps[prow1 + col]     = f2tf(p2);
                    Ps[prow1 + col + 1] = f2tf(p3);
                }
                l[mt][0] += rs0;
                l[mt][1] += rs1;
            }
            __syncwarp();

            // O += P V
#pragma unroll
            for (int ks = 0; ks < 8; ks++) {
                int kk = ks * 8;
                uint32_t b[8][2];
#pragma unroll
                for (int vt = 0; vt < 8; vt++) {
                    b[vt][0] = Vc[(kk + qc) * AVS + vt * 8 + qr];
                    b[vt][1] = Vc[(kk + qc + 4) * AVS + vt * 8 + qr];
                }
#pragma unroll
                for (int mt = 0; mt < 2; mt++) {
                    int prow0 = (w * 32 + mt * 16 + qr) * APS;
                    int prow1 = (w * 32 + mt * 16 + qr + 8) * APS;
                    uint32_t a0 = Ps[prow0 + kk + qc];
                    uint32_t a1 = Ps[prow1 + kk + qc];
                    uint32_t a2 = Ps[prow0 + kk + qc + 4];
                    uint32_t a3 = Ps[prow1 + kk + qc + 4];
#pragma unroll
                    for (int vt = 0; vt < 8; vt++)
                        MMA_TF32(o[mt][vt], a0, a1, a2, a3, b[vt][0], b[vt][1]);
                }
            }
            __syncwarp();   // P reads done before next chunk overwrites Ps rows
        }
    }

    // epilogue (tf32 out)
#pragma unroll
    for (int mt = 0; mt < 2; mt++) {
        float l0 = l[mt][0], l1 = l[mt][1];
        l0 += __shfl_xor_sync(0xffffffffu, l0, 1);
        l0 += __shfl_xor_sync(0xffffffffu, l0, 2);
        l1 += __shfl_xor_sync(0xffffffffu, l1, 1);
        l1 += __shfl_xor_sync(0xffffffffu, l1, 2);
        float inv0 = 1.f / l0;
        float inv1 = 1.f / l1;
        int row = rb + q0 + w * 32 + mt * 16 + qr;
#pragma unroll
        for (int vt = 0; vt < 8; vt++) {
            int col = cq + vt * 8 + 2 * qc;
            float2 v0, v1;
            v0.x = __uint_as_float(f2tf(o[mt][vt][0] * inv0));
            v0.y = __uint_as_float(f2tf(o[mt][vt][1] * inv0));
            v1.x = __uint_as_float(f2tf(o[mt][vt][2] * inv1));
            v1.y = __uint_as_float(f2tf(o[mt][vt][3] * inv1));
            *(float2*)&Out[(size_t)row * DD + col] = v0;
            *(float2*)&Out[(size_t)(row + 8) * DD + col] = v1;
        }
    }
}

// ---------------- fused residual + LayerNorm (+relu / tf32-out) -------------
__global__ __launch_bounds__(128) void add_ln_kernel(
    const float* __restrict__ X, const float* __restrict__ R,
    const float* __restrict__ gamma, const float* __restrict__ beta,
    float* __restrict__ out, int relu, int tf32_out)
{
    const int row = blockIdx.x;
    const int tid = threadIdx.x;

    float4 xv = *(const float4*)&X[(size_t)row * DD + tid * 4];
    float4 rv = *(const float4*)&R[(size_t)row * DD + tid * 4];
    float v[4] = { xv.x + rv.x, xv.y + rv.y, xv.z + rv.z, xv.w + rv.w };

    float s = v[0] + v[1] + v[2] + v[3];
    float sq = v[0] * v[0] + v[1] * v[1] + v[2] * v[2] + v[3] * v[3];
#pragma unroll
    for (int off = 16; off >= 1; off >>= 1) {
        s += __shfl_xor_sync(0xffffffffu, s, off);
        sq += __shfl_xor_sync(0xffffffffu, sq, off);
    }
    __shared__ float sw[4], sqw[4];
    int w = tid >> 5;
    if ((tid & 31) == 0) { sw[w] = s; sqw[w] = sq; }
    __syncthreads();
    s = sw[0] + sw[1] + sw[2] + sw[3];
    sq = sqw[0] + sqw[1] + sqw[2] + sqw[3];

    float mean = s * (1.0f / (float)DD);
    float var = sq * (1.0f / (float)DD) - mean * mean;
    float rstd = rsqrtf(var + 1e-5f);

    float4 gv = *(const float4*)&gamma[tid * 4];
    float4 bv = *(const float4*)&beta[tid * 4];
    float ga[4] = { gv.x, gv.y, gv.z, gv.w };
    float be[4] = { bv.x, bv.y, bv.z, bv.w };

    float ov[4];
#pragma unroll
    for (int j = 0; j < 4; j++) {
        float t = (v[j] - mean) * rstd * ga[j] + be[j];
        if (relu) t = fmaxf(t, 0.f);
        if (tf32_out) t = __uint_as_float(f2tf(t));
        ov[j] = t;
    }
    *(float4*)&out[(size_t)row * DD + tid * 4] = *(float4*)ov;
}

// ---------------- launch ------------------------------------------------------
extern "C" void kernel_launch(void* const* d_in, const int* in_sizes, int n_in,
                              void* d_out, int out_size)
{
    (void)in_sizes; (void)n_in; (void)out_size;

    const int*   x    = (const int*)  d_in[0];
    const float* emb  = (const float*)d_in[1];
    const float* WfQ  = (const float*)d_in[2];
    const float* bfQ  = (const float*)d_in[3];
    const float* WfK  = (const float*)d_in[4];
    const float* bfK  = (const float*)d_in[5];
    const float* WfV  = (const float*)d_in[6];
    const float* bfV  = (const float*)d_in[7];
    const float* WQ   = (const float*)d_in[8];
    const float* bQ   = (const float*)d_in[9];
    const float* WK   = (const float*)d_in[10];
    const float* bK   = (const float*)d_in[11];
    const float* WV   = (const float*)d_in[12];
    const float* bV   = (const float*)d_in[13];
    const float* Wo   = (const float*)d_in[14];
    const float* bo   = (const float*)d_in[15];
    const float* W1   = (const float*)d_in[16];
    const float* b1   = (const float*)d_in[17];
    const float* W2   = (const float*)d_in[18];
    const float* b2   = (const float*)d_in[19];
    const float* gamma= (const float*)d_in[20];
    const float* beta = (const float*)d_in[21];
    float* out = (float*)d_out;

    float* base = nullptr;
    cudaGetSymbolAddress((void**)&base, g_scratch);

    float* Z    = base + 0 * (size_t)NT;
    float* QKVH = base + 1 * (size_t)NT;     // 8192 x 1536 (tf32 bits)
    float* ATT  = base + 4 * (size_t)NT;     // tf32 bits
    float* AO   = base + 5 * (size_t)NT;     // fp32
    float* Aa   = base + 6 * (size_t)NT;     // tf32 bits
    float* H1   = base + 7 * (size_t)NT;     // 8192 x 2048 tf32 bits
    float* F    = base + 11 * (size_t)NT;    // fp32
    float* WQr  = base + 12 * (size_t)NT;    // tf32
    float* WKr  = WQr + DD * DD;
    float* WVr  = WKr + DD * DD;
    float* Wqkv = WVr + DD * DD;             // 512 x 1536 tf32
    float* bqkv = Wqkv + 3 * DD * DD;        // 1536 fp32
    float* Wpart= bqkv + 2048;               // 4 x (512 x 1536) fp32 partials

    cudaFuncSetAttribute(attention_kernel,
                         cudaFuncAttributeMaxDynamicSharedMemorySize, ATT_SMEM);

    // 1. merged prep: embed+PE || repack || bias-compose
    prep_kernel<<<PREP_BLOCKS, 256>>>(x, emb, WQ, WK, WV, bfQ, bfK, bfV,
                                      bQ, bK, bV, Z, WQr, WKr, WVr, bqkv);

    // 2. split-K batched weight composition + merge
    gemm_compose_splitk_kernel<<<dim3(DD / 128, DD / 128, 12), 256>>>(
        WfQ, WfK, WfV, WQr, WKr, WVr, Wpart);
    compose_merge_kernel<<<(3 * DD * DD + 255) / 256, 256>>>(Wpart, Wqkv);

    // 3. fused QKV head projection -> tf32 bits, Q pre-scaled
    dim3 gqkv(3 * DD / 128, NTOK / 128);
    gemm_tf32_kernel<<<gqkv, 256>>>(NTOK, 3 * DD, DD, 3 * DD, Z, Wqkv, bqkv, QKVH, 2);

    // 4. attention (128-row KV staging)
    attention_kernel<<<dim3(SS / QROWS, BB * HH), 256, ATT_SMEM>>>(
        QKVH, QKVH + DD, QKVH + 2 * DD, 3 * DD, ATT);

    // 5. output projection (fp32 out) + residual LN (tf32 out)
    dim3 g512(DD / 128, NTOK / 128);
    gemm_tf32_kernel<<<g512, 256>>>(NTOK, DD, DD, DD, ATT, Wo, bo, AO, 0);
    add_ln_kernel<<<NTOK, 128>>>(AO, Z, gamma, beta, Aa, 0, 1);

    // 6. FFN
    dim3 gff(DFF / 128, NTOK / 128);
    gemm_tf32_kernel<<<gff, 256>>>(NTOK, DFF, DD, DFF, Aa, W1, b1, H1, 1);
    gemm_tf32_kernel<<<g512, 256>>>(NTOK, DD, DFF, DD, H1, W2, b2, F, 0);

    // 7. residual LN + final relu -> fp32 output
    add_ln_kernel<<<NTOK, 128>>>(F, Aa, gamma, beta, out, 1, 0);
}

// round 17
// speedup vs baseline: 1.1151x; 1.0918x over previous
#include <cuda_runtime.h>
#include <math.h>
#include <stdint.h>

// ---------------- problem constants ----------------
#define BB 4
#define SS 2048
#define DD 512
#define HH 8
#define DHEAD 64
#define DFF 2048
#define NTOK (BB*SS)          // 8192 tokens
#define NT (NTOK*DD)          // 4194304 floats per [tokens, 512] buffer

// ---------------- scratch ----------------
__device__ float g_scratch[12*(size_t)NT + 6*DD*DD + 2048 + 12*DD*DD];

// ---------------- helpers ----------------
__device__ __forceinline__ uint32_t f2tf(float x) {
    uint32_t u;
    asm("cvt.rna.tf32.f32 %0, %1;" : "=r"(u) : "f"(x));
    return u;
}

__device__ __forceinline__ float ex2(float x) {
    float y;
    asm("ex2.approx.f32 %0, %1;" : "=f"(y) : "f"(x));
    return y;
}

#define MMA_TF32(d, a0, a1, a2, a3, b0, b1)                                \
    asm volatile("mma.sync.aligned.m16n8k8.row.col.f32.tf32.tf32.f32 "     \
        "{%0,%1,%2,%3}, {%4,%5,%6,%7}, {%8,%9}, {%0,%1,%2,%3};"            \
        : "+f"(d[0]), "+f"(d[1]), "+f"(d[2]), "+f"(d[3])                   \
        : "r"(a0), "r"(a1), "r"(a2), "r"(a3), "r"(b0), "r"(b1))

// scale folded into Q at GEMM epilogue: 1/sqrt(64) * log2(e)
#define QSCALE 0.180336880f

// ---------------- merged prep: embed+PE | repack3 | bias-compose ------------
#define PREP_EMBED_BLOCKS (SS * DD / 256)          // 4096
#define PREP_REPACK_BLOCKS (3 * DD * DD / 256)     // 3072
#define PREP_BIAS_BLOCKS 6
#define PREP_BLOCKS (PREP_EMBED_BLOCKS + PREP_REPACK_BLOCKS + PREP_BIAS_BLOCKS)

__global__ void prep_kernel(
    const int* __restrict__ x, const float* __restrict__ emb,
    const float* __restrict__ WQ, const float* __restrict__ WK, const float* __restrict__ WV,
    const float* __restrict__ bfQ, const float* __restrict__ bfK, const float* __restrict__ bfV,
    const float* __restrict__ bQ,  const float* __restrict__ bK,  const float* __restrict__ bV,
    float* __restrict__ z,
    float* __restrict__ WQr, float* __restrict__ WKr, float* __restrict__ WVr,
    float* __restrict__ bqkv)
{
    int blk = blockIdx.x;
    if (blk < PREP_EMBED_BLOCKS) {
        int idx = blk * 256 + threadIdx.x;
        int d = idx & (DD - 1);
        int s = idx >> 9;
        float di = (float)d * (1.0f / (float)DD);
        float ang = (float)s / powf(10000.0f, di);
        float pe = (d & 1) ? cosf(ang) : sinf(ang);
#pragma unroll
        for (int b = 0; b < BB; b++) {
            int t = b * SS + s;
            z[(size_t)t * DD + d] = __uint_as_float(f2tf(emb[(size_t)x[t] * DD + d] + pe));
        }
    } else if (blk < PREP_EMBED_BLOCKS + PREP_REPACK_BLOCKS) {
        int gidx = (blk - PREP_EMBED_BLOCKS) * 256 + threadIdx.x;
        int which = gidx / (DD * DD);
        int idx = gidx - which * (DD * DD);
        const float* W = (which == 0) ? WQ : (which == 1) ? WK : WV;
        float* Wr = (which == 0) ? WQr : (which == 1) ? WKr : WVr;
        int n = idx & (DD - 1);
        int d = idx >> 9;
        int h = n >> 6, k = n & 63;
        Wr[idx] = __uint_as_float(f2tf(W[((size_t)h * DD + d) * DHEAD + k]));
    } else {
        int g = (blk - PREP_EMBED_BLOCKS - PREP_REPACK_BLOCKS) * 256 + threadIdx.x;
        if (g >= 3 * DD) return;
        int which = g >> 9;
        int n = g & (DD - 1);
        const float* bf = (which == 0) ? bfQ : (which == 1) ? bfK : bfV;
        const float* W  = (which == 0) ? WQ : (which == 1) ? WK : WV;
        const float* bh = (which == 0) ? bQ : (which == 1) ? bK : bV;
        int h = n >> 6, kk = n & 63;
        float s = bh[n];
        for (int k = 0; k < DD; k++)
            s += bf[k] * __uint_as_float(f2tf(W[((size_t)h * DD + k) * DHEAD + kk]));
        bqkv[g] = s;
    }
}

// ---------------- tf32 GEMM: 4 warps, 64x64 warp tiles (LDS-optimized) ------
// CTA 128x128, 128 threads as 2m x 2n warps. 128 B/mma fragment traffic.
#define GS_A 20
#define GS_B 136

__global__ __launch_bounds__(128, 2) void gemm_tf32_kernel(
    int M, int N, int K, int ldc,
    const float* __restrict__ A, const float* __restrict__ W,
    const float* __restrict__ bias, float* __restrict__ C, int mode)
{
    __shared__ uint32_t As[128 * GS_A];
    __shared__ uint32_t Bs[16 * GS_B];

    const int tid  = threadIdx.x;
    const int warp = tid >> 5;
    const int lane = tid & 31;
    const int qr   = lane >> 2;
    const int qc   = lane & 3;
    const int wm   = warp & 1;       // m offset wm*64
    const int wn   = warp >> 1;      // n offset wn*64
    const int m0   = blockIdx.y * 128;
    const int n0   = blockIdx.x * 128;

    float acc[4][8][4];
#pragma unroll
    for (int i = 0; i < 4; i++)
#pragma unroll
        for (int j = 0; j < 8; j++)
#pragma unroll
            for (int c = 0; c < 4; c++) acc[i][j][c] = 0.f;

    float4 ar[4], br[4];
#pragma unroll
    for (int p = 0; p < 4; p++) {
        int idx = p * 128 + tid;
        int arow = idx >> 2, ac = (idx & 3) * 4;
        ar[p] = *(const float4*)&A[(size_t)(m0 + arow) * K + ac];
        int krow = idx >> 5, nc = (idx & 31) * 4;
        br[p] = *(const float4*)&W[(size_t)krow * N + n0 + nc];
    }

    for (int k0 = 0; k0 < K; k0 += 16) {
        __syncthreads();
#pragma unroll
        for (int p = 0; p < 4; p++) {
            int idx = p * 128 + tid;
            int arow = idx >> 2, ac = (idx & 3) * 4;
            As[arow * GS_A + ac + 0] = f2tf(ar[p].x);
            As[arow * GS_A + ac + 1] = f2tf(ar[p].y);
            As[arow * GS_A + ac + 2] = f2tf(ar[p].z);
            As[arow * GS_A + ac + 3] = f2tf(ar[p].w);
            int krow = idx >> 5, nc = (idx & 31) * 4;
            Bs[krow * GS_B + nc + 0] = f2tf(br[p].x);
            Bs[krow * GS_B + nc + 1] = f2tf(br[p].y);
            Bs[krow * GS_B + nc + 2] = f2tf(br[p].z);
            Bs[krow * GS_B + nc + 3] = f2tf(br[p].w);
        }
        __syncthreads();

        if (k0 + 16 < K) {
#pragma unroll
            for (int p = 0; p < 4; p++) {
                int idx = p * 128 + tid;
                int arow = idx >> 2, ac = (idx & 3) * 4;
                ar[p] = *(const float4*)&A[(size_t)(m0 + arow) * K + k0 + 16 + ac];
                int krow = idx >> 5, nc = (idx & 31) * 4;
                br[p] = *(const float4*)&W[(size_t)(k0 + 16 + krow) * N + n0 + nc];
            }
        }

#pragma unroll
        for (int kk = 0; kk < 16; kk += 8) {
            uint32_t af[4][4], bf[8][2];
#pragma unroll
            for (int mt = 0; mt < 4; mt++) {
                int mrow = wm * 64 + mt * 16 + qr;
                af[mt][0] = As[mrow * GS_A + kk + qc];
                af[mt][1] = As[(mrow + 8) * GS_A + kk + qc];
                af[mt][2] = As[mrow * GS_A + kk + qc + 4];
                af[mt][3] = As[(mrow + 8) * GS_A + kk + qc + 4];
            }
#pragma unroll
            for (int nt = 0; nt < 8; nt++) {
                int ncol = wn * 64 + nt * 8 + qr;
                bf[nt][0] = Bs[(kk + qc) * GS_B + ncol];
                bf[nt][1] = Bs[(kk + qc + 4) * GS_B + ncol];
            }
#pragma unroll
            for (int mt = 0; mt < 4; mt++)
#pragma unroll
                for (int nt = 0; nt < 8; nt++)
                    MMA_TF32(acc[mt][nt], af[mt][0], af[mt][1], af[mt][2], af[mt][3],
                             bf[nt][0], bf[nt][1]);
        }
    }

    // epilogue
#pragma unroll
    for (int mt = 0; mt < 4; mt++) {
        int row = m0 + wm * 64 + mt * 16 + qr;
#pragma unroll
        for (int nt = 0; nt < 8; nt++) {
            int col = n0 + wn * 64 + nt * 8 + qc * 2;
            float2 bv = bias ? *(const float2*)&bias[col] : make_float2(0.f, 0.f);
            float2 v0, v1;
            v0.x = acc[mt][nt][0] + bv.x;
            v0.y = acc[mt][nt][1] + bv.y;
            v1.x = acc[mt][nt][2] + bv.x;
            v1.y = acc[mt][nt][3] + bv.y;
            if (mode == 1) {
                v0.x = __uint_as_float(f2tf(fmaxf(v0.x, 0.f)));
                v0.y = __uint_as_float(f2tf(fmaxf(v0.y, 0.f)));
                v1.x = __uint_as_float(f2tf(fmaxf(v1.x, 0.f)));
                v1.y = __uint_as_float(f2tf(fmaxf(v1.y, 0.f)));
            } else if (mode == 2) {
                float sc = (col < DD) ? QSCALE : 1.0f;
                v0.x = __uint_as_float(f2tf(v0.x * sc));
                v0.y = __uint_as_float(f2tf(v0.y * sc));
                v1.x = __uint_as_float(f2tf(v1.x * sc));
                v1.y = __uint_as_float(f2tf(v1.y * sc));
            } else if (mode == 3) {
                v0.x = __uint_as_float(f2tf(v0.x));
                v0.y = __uint_as_float(f2tf(v0.y));
                v1.x = __uint_as_float(f2tf(v1.x));
                v1.y = __uint_as_float(f2tf(v1.y));
            }
            *(float2*)&C[(size_t)row * ldc + col] = v0;
            *(float2*)&C[(size_t)(row + 8) * ldc + col] = v1;
        }
    }
}

// ---------------- split-K compose GEMM (cold path, unchanged shape) ---------
__global__ __launch_bounds__(256, 2) void gemm_compose_splitk_kernel(
    const float* __restrict__ WfQ, const float* __restrict__ WfK, const float* __restrict__ WfV,
    const float* __restrict__ WQr, const float* __restrict__ WKr, const float* __restrict__ WVr,
    float* __restrict__ Wpart)
{
    const int z = blockIdx.z;
    const int mat = z >> 2;
    const int kq  = z & 3;
    const float* A = (mat == 0) ? WfQ : (mat == 1) ? WfK : WfV;
    const float* W = (mat == 0) ? WQr : (mat == 1) ? WKr : WVr;
    float* C = Wpart + (size_t)kq * DD * 3 * DD + mat * DD;
    const int ldc = 3 * DD;
    const int kbase = kq * 128;

    __shared__ uint32_t As[128 * GS_A];
    __shared__ uint32_t Bs[16 * GS_B];

    const int tid  = threadIdx.x;
    const int warp = tid >> 5;
    const int lane = tid & 31;
    const int qr   = lane >> 2;
    const int qc   = lane & 3;
    const int wm   = warp & 1;
    const int wn   = warp >> 1;
    const int m0   = blockIdx.y * 128;
    const int n0   = blockIdx.x * 128;

    float acc[4][4][4];
#pragma unroll
    for (int i = 0; i < 4; i++)
#pragma unroll
        for (int j = 0; j < 4; j++)
#pragma unroll
            for (int c = 0; c < 4; c++) acc[i][j][c] = 0.f;

    float4 ar[2], br[2];
#pragma unroll
    for (int p = 0; p < 2; p++) {
        int idx = p * 256 + tid;
        int arow = idx >> 2, ac = (idx & 3) * 4;
        ar[p] = *(const float4*)&A[(size_t)(m0 + arow) * DD + kbase + ac];
        int krow = idx >> 5, nc = (idx & 31) * 4;
        br[p] = *(const float4*)&W[(size_t)(kbase + krow) * DD + n0 + nc];
    }

    for (int k0 = 0; k0 < 128; k0 += 16) {
        __syncthreads();
#pragma unroll
        for (int p = 0; p < 2; p++) {
            int idx = p * 256 + tid;
            int arow = idx >> 2, ac = (idx & 3) * 4;
            As[arow * GS_A + ac + 0] = f2tf(ar[p].x);
            As[arow * GS_A + ac + 1] = f2tf(ar[p].y);
            As[arow * GS_A + ac + 2] = f2tf(ar[p].z);
            As[arow * GS_A + ac + 3] = f2tf(ar[p].w);
            int krow = idx >> 5, nc = (idx & 31) * 4;
            Bs[krow * GS_B + nc + 0] = f2tf(br[p].x);
            Bs[krow * GS_B + nc + 1] = f2tf(br[p].y);
            Bs[krow * GS_B + nc + 2] = f2tf(br[p].z);
            Bs[krow * GS_B + nc + 3] = f2tf(br[p].w);
        }
        __syncthreads();

        if (k0 + 16 < 128) {
#pragma unroll
            for (int p = 0; p < 2; p++) {
                int idx = p * 256 + tid;
                int arow = idx >> 2, ac = (idx & 3) * 4;
                ar[p] = *(const float4*)&A[(size_t)(m0 + arow) * DD + kbase + k0 + 16 + ac];
                int krow = idx >> 5, nc = (idx & 31) * 4;
                br[p] = *(const float4*)&W[(size_t)(kbase + k0 + 16 + krow) * DD + n0 + nc];
            }
        }

#pragma unroll
        for (int kk = 0; kk < 16; kk += 8) {
            uint32_t af[4][4], bf[4][2];
#pragma unroll
            for (int mt = 0; mt < 4; mt++) {
                int mrow = wm * 64 + mt * 16 + qr;
                af[mt][0] = As[mrow * GS_A + kk + qc];
                af[mt][1] = As[(mrow + 8) * GS_A + kk + qc];
                af[mt][2] = As[mrow * GS_A + kk + qc + 4];
                af[mt][3] = As[(mrow + 8) * GS_A + kk + qc + 4];
            }
#pragma unroll
            for (int nt = 0; nt < 4; nt++) {
                int ncol = wn * 32 + nt * 8 + qr;
                bf[nt][0] = Bs[(kk + qc) * GS_B + ncol];
                bf[nt][1] = Bs[(kk + qc + 4) * GS_B + ncol];
            }
#pragma unroll
            for (int mt = 0; mt < 4; mt++)
#pragma unroll
                for (int nt = 0; nt < 4; nt++)
                    MMA_TF32(acc[mt][nt], af[mt][0], af[mt][1], af[mt][2], af[mt][3],
                             bf[nt][0], bf[nt][1]);
        }
    }

#pragma unroll
    for (int mt = 0; mt < 4; mt++) {
        int row = m0 + wm * 64 + mt * 16 + qr;
#pragma unroll
        for (int nt = 0; nt < 4; nt++) {
            int col = n0 + wn * 32 + nt * 8 + qc * 2;
            float2 v0, v1;
            v0.x = acc[mt][nt][0]; v0.y = acc[mt][nt][1];
            v1.x = acc[mt][nt][2]; v1.y = acc[mt][nt][3];
            *(float2*)&C[(size_t)row * ldc + col] = v0;
            *(float2*)&C[(size_t)(row + 8) * ldc + col] = v1;
        }
    }
}

// ---------------- merge split-K partials -> tf32 Wqkv -----------------------
__global__ void compose_merge_kernel(const float* __restrict__ Wpart,
                                     float* __restrict__ Wqkv)
{
    const int n = DD * 3 * DD;
    int i = blockIdx.x * blockDim.x + threadIdx.x;
    if (i >= n) return;
    float s = Wpart[i] + Wpart[i + n] + Wpart[i + 2 * n] + Wpart[i + 3 * n];
    Wqkv[i] = __uint_as_float(f2tf(s));
}

// ---------------- flash attention: 128-row KV staging, no-max softmax -------
#define AKS 68
#define AVS 72
#define APS 68
#define QROWS 256
#define ATT_SMEM ((128*AKS + 128*AVS + QROWS*APS) * (int)sizeof(uint32_t))

__global__ __launch_bounds__(256, 1) void attention_kernel(
    const float* __restrict__ Qh, const float* __restrict__ Kh,
    const float* __restrict__ Vh, int ld, float* __restrict__ Out)
{
    extern __shared__ uint32_t sm[];
    uint32_t* Ks = sm;
    uint32_t* Vs = Ks + 128 * AKS;
    uint32_t* Ps = Vs + 128 * AVS;

    const int tid  = threadIdx.x;
    const int w    = tid >> 5;
    const int lane = tid & 31;
    const int qr   = lane >> 2;
    const int qc   = lane & 3;
    const int q0   = blockIdx.x * QROWS;
    const int bh   = blockIdx.y;
    const int rb   = (bh >> 3) * SS;
    const int cq   = (bh & 7) * DHEAD;

#pragma unroll
    for (int p = 0; p < 16; ++p) {
        int idx = p * 256 + tid;
        int r = idx >> 4, kc = (idx & 15) * 4;
        uint4 u = *(const uint4*)&Qh[(size_t)(rb + q0 + r) * ld + cq + kc];
        *(uint4*)&Ps[r * APS + kc] = u;
    }
    __syncthreads();

    uint32_t qf[2][8][4];
#pragma unroll
    for (int mt = 0; mt < 2; mt++) {
        int base0 = (w * 32 + mt * 16 + qr) * APS;
        int base1 = (w * 32 + mt * 16 + qr + 8) * APS;
#pragma unroll
        for (int ks = 0; ks < 8; ks++) {
            int kk = ks * 8;
            qf[mt][ks][0] = Ps[base0 + kk + qc];
            qf[mt][ks][1] = Ps[base1 + kk + qc];
            qf[mt][ks][2] = Ps[base0 + kk + qc + 4];
            qf[mt][ks][3] = Ps[base1 + kk + qc + 4];
        }
    }

    float l[2][2];
    float o[2][8][4];
#pragma unroll
    for (int mt = 0; mt < 2; mt++) {
        l[mt][0] = 0.f; l[mt][1] = 0.f;
#pragma unroll
        for (int i = 0; i < 8; i++)
#pragma unroll
            for (int c = 0; c < 4; c++) o[mt][i][c] = 0.f;
    }

    for (int s0 = 0; s0 < SS; s0 += 128) {
        __syncthreads();
#pragma unroll
        for (int p = 0; p < 8; p++) {
            int idx = p * 256 + tid;
            int r = idx >> 4, kc = (idx & 15) * 4;
            uint4 uk = *(const uint4*)&Kh[(size_t)(rb + s0 + r) * ld + cq + kc];
            uint4 uv = *(const uint4*)&Vh[(size_t)(rb + s0 + r) * ld + cq + kc];
            *(uint4*)&Ks[r * AKS + kc] = uk;
            *(uint4*)&Vs[r * AVS + kc] = uv;
        }
        __syncthreads();

#pragma unroll
        for (int chunk = 0; chunk < 2; chunk++) {
            uint32_t* Kc = Ks + chunk * 64 * AKS;
            uint32_t* Vc = Vs + chunk * 64 * AVS;

            float s[2][8][4];
#pragma unroll
            for (int mt = 0; mt < 2; mt++)
#pragma unroll
                for (int nt = 0; nt < 8; nt++)
#pragma unroll
                    for (int c = 0; c < 4; c++) s[mt][nt][c] = 0.f;

#pragma unroll
            for (int ks = 0; ks < 8; ks++) {
                int kk = ks * 8;
#pragma unroll
                for (int nt = 0; nt < 8; nt++) {
                    uint32_t b0 = Kc[(nt * 8 + qr) * AKS + kk + qc];
                    uint32_t b1 = Kc[(nt * 8 + qr) * AKS + kk + qc + 4];
                    MMA_TF32(s[0][nt], qf[0][ks][0], qf[0][ks][1], qf[0][ks][2], qf[0][ks][3], b0, b1);
                    MMA_TF32(s[1][nt], qf[1][ks][0], qf[1][ks][1], qf[1][ks][2], qf[1][ks][3], b0, b1);
                }
            }

            // no-max softmax
#pragma unroll
            for (int mt = 0; mt < 2; mt++) {
                int prow0 = (w * 32 + mt * 16 + qr) * APS;
                int prow1 = (w * 32 + mt * 16 + qr + 8) * APS;
                float rs0 = 0.f, rs1 = 0.f;
#pragma unroll
                for (int nt = 0; nt < 8; nt++) {
                    float p0 = ex2(s[mt][nt][0]);
                    float p1 = ex2(s[mt][nt][1]);
                    float p2 = ex2(s[mt][nt][2]);
                    float p3 = ex2(s[mt][nt][3]);
                    rs0 += p0 + p1;
                    rs1 += p2 + p3;
                    int col = nt * 8 + 2 * qc;
                    Ps[prow0 + col]     = f2tf(p0);
                    Ps[prow0 + col + 1] = f2tf(p1);
                    Ps[prow1 + col]     = f2tf(p2);
                    Ps[prow1 + col + 1] = f2tf(p3);
                }
                l[mt][0] += rs0;
                l[mt][1] += rs1;
            }
            __syncwarp();

            // O += P V
#pragma unroll
            for (int ks = 0; ks < 8; ks++) {
                int kk = ks * 8;
                uint32_t b[8][2];
#pragma unroll
                for (int vt = 0; vt < 8; vt++) {
                    b[vt][0] = Vc[(kk + qc) * AVS + vt * 8 + qr];
                    b[vt][1] = Vc[(kk + qc + 4) * AVS + vt * 8 + qr];
                }
#pragma unroll
                for (int mt = 0; mt < 2; mt++) {
                    int prow0 = (w * 32 + mt * 16 + qr) * APS;
                    int prow1 = (w * 32 + mt * 16 + qr + 8) * APS;
                    uint32_t a0 = Ps[prow0 + kk + qc];
                    uint32_t a1 = Ps[prow1 + kk + qc];
                    uint32_t a2 = Ps[prow0 + kk + qc + 4];
                    uint32_t a3 = Ps[prow1 + kk + qc + 4];
#pragma unroll
                    for (int vt = 0; vt < 8; vt++)
                        MMA_TF32(o[mt][vt], a0, a1, a2, a3, b[vt][0], b[vt][1]);
                }
            }
            __syncwarp();
        }
    }

    // epilogue (tf32 out)
#pragma unroll
    for (int mt = 0; mt < 2; mt++) {
        float l0 = l[mt][0], l1 = l[mt][1];
        l0 += __shfl_xor_sync(0xffffffffu, l0, 1);
        l0 += __shfl_xor_sync(0xffffffffu, l0, 2);
        l1 += __shfl_xor_sync(0xffffffffu, l1, 1);
        l1 += __shfl_xor_sync(0xffffffffu, l1, 2);
        float inv0 = 1.f / l0;
        float inv1 = 1.f / l1;
        int row = rb + q0 + w * 32 + mt * 16 + qr;
#pragma unroll
        for (int vt = 0; vt < 8; vt++) {
            int col = cq + vt * 8 + 2 * qc;
            float2 v0, v1;
            v0.x = __uint_as_float(f2tf(o[mt][vt][0] * inv0));
            v0.y = __uint_as_float(f2tf(o[mt][vt][1] * inv0));
            v1.x = __uint_as_float(f2tf(o[mt][vt][2] * inv1));
            v1.y = __uint_as_float(f2tf(o[mt][vt][3] * inv1));
            *(float2*)&Out[(size_t)row * DD + col] = v0;
            *(float2*)&Out[(size_t)(row + 8) * DD + col] = v1;
        }
    }
}

// ---------------- fused residual + LayerNorm (+relu / tf32-out) -------------
__global__ __launch_bounds__(128) void add_ln_kernel(
    const float* __restrict__ X, const float* __restrict__ R,
    const float* __restrict__ gamma, const float* __restrict__ beta,
    float* __restrict__ out, int relu, int tf32_out)
{
    const int row = blockIdx.x;
    const int tid = threadIdx.x;

    float4 xv = *(const float4*)&X[(size_t)row * DD + tid * 4];
    float4 rv = *(const float4*)&R[(size_t)row * DD + tid * 4];
    float v[4] = { xv.x + rv.x, xv.y + rv.y, xv.z + rv.z, xv.w + rv.w };

    float s = v[0] + v[1] + v[2] + v[3];
    float sq = v[0] * v[0] + v[1] * v[1] + v[2] * v[2] + v[3] * v[3];
#pragma unroll
    for (int off = 16; off >= 1; off >>= 1) {
        s += __shfl_xor_sync(0xffffffffu, s, off);
        sq += __shfl_xor_sync(0xffffffffu, sq, off);
    }
    __shared__ float sw[4], sqw[4];
    int w = tid >> 5;
    if ((tid & 31) == 0) { sw[w] = s; sqw[w] = sq; }
    __syncthreads();
    s = sw[0] + sw[1] + sw[2] + sw[3];
    sq = sqw[0] + sqw[1] + sqw[2] + sqw[3];

    float mean = s * (1.0f / (float)DD);
    float var = sq * (1.0f / (float)DD) - mean * mean;
    float rstd = rsqrtf(var + 1e-5f);

    float4 gv = *(const float4*)&gamma[tid * 4];
    float4 bv = *(const float4*)&beta[tid * 4];
    float ga[4] = { gv.x, gv.y, gv.z, gv.w };
    float be[4] = { bv.x, bv.y, bv.z, bv.w };

    float ov[4];
#pragma unroll
    for (int j = 0; j < 4; j++) {
        float t = (v[j] - mean) * rstd * ga[j] + be[j];
        if (relu) t = fmaxf(t, 0.f);
        if (tf32_out) t = __uint_as_float(f2tf(t));
        ov[j] = t;
    }
    *(float4*)&out[(size_t)row * DD + tid * 4] = *(float4*)ov;
}

// ---------------- launch ------------------------------------------------------
extern "C" void kernel_launch(void* const* d_in, const int* in_sizes, int n_in,
                              void* d_out, int out_size)
{
    (void)in_sizes; (void)n_in; (void)out_size;

    const int*   x    = (const int*)  d_in[0];
    const float* emb  = (const float*)d_in[1];
    const float* WfQ  = (const float*)d_in[2];
    const float* bfQ  = (const float*)d_in[3];
    const float* WfK  = (const float*)d_in[4];
    const float* bfK  = (const float*)d_in[5];
    const float* WfV  = (const float*)d_in[6];
    const float* bfV  = (const float*)d_in[7];
    const float* WQ   = (const float*)d_in[8];
    const float* bQ   = (const float*)d_in[9];
    const float* WK   = (const float*)d_in[10];
    const float* bK   = (const float*)d_in[11];
    const float* WV   = (const float*)d_in[12];
    const float* bV   = (const float*)d_in[13];
    const float* Wo   = (const float*)d_in[14];
    const float* bo   = (const float*)d_in[15];
    const float* W1   = (const float*)d_in[16];
    const float* b1   = (const float*)d_in[17];
    const float* W2   = (const float*)d_in[18];
    const float* b2   = (const float*)d_in[19];
    const float* gamma= (const float*)d_in[20];
    const float* beta = (const float*)d_in[21];
    float* out = (float*)d_out;

    float* base = nullptr;
    cudaGetSymbolAddress((void**)&base, g_scratch);

    float* Z    = base + 0 * (size_t)NT;
    float* QKVH = base + 1 * (size_t)NT;
    float* ATT  = base + 4 * (size_t)NT;
    float* AO   = base + 5 * (size_t)NT;
    float* Aa   = base + 6 * (size_t)NT;
    float* H1   = base + 7 * (size_t)NT;
    float* F    = base + 11 * (size_t)NT;
    float* WQr  = base + 12 * (size_t)NT;
    float* WKr  = WQr + DD * DD;
    float* WVr  = WKr + DD * DD;
    float* Wqkv = WVr + DD * DD;
    float* bqkv = Wqkv + 3 * DD * DD;
    float* Wpart= bqkv + 2048;

    cudaFuncSetAttribute(attention_kernel,
                         cudaFuncAttributeMaxDynamicSharedMemorySize, ATT_SMEM);

    // 1. merged prep
    prep_kernel<<<PREP_BLOCKS, 256>>>(x, emb, WQ, WK, WV, bfQ, bfK, bfV,
                                      bQ, bK, bV, Z, WQr, WKr, WVr, bqkv);

    // 2. split-K weight composition + merge
    gemm_compose_splitk_kernel<<<dim3(DD / 128, DD / 128, 12), 256>>>(
        WfQ, WfK, WfV, WQr, WKr, WVr, Wpart);
    compose_merge_kernel<<<(3 * DD * DD + 255) / 256, 256>>>(Wpart, Wqkv);

    // 3. fused QKV head projection (128-thread GEMM)
    dim3 gqkv(3 * DD / 128, NTOK / 128);
    gemm_tf32_kernel<<<gqkv, 128>>>(NTOK, 3 * DD, DD, 3 * DD, Z, Wqkv, bqkv, QKVH, 2);

    // 4. attention
    attention_kernel<<<dim3(SS / QROWS, BB * HH), 256, ATT_SMEM>>>(
        QKVH, QKVH + DD, QKVH + 2 * DD, 3 * DD, ATT);

    // 5. output projection + residual LN
    dim3 g512(DD / 128, NTOK / 128);
    gemm_tf32_kernel<<<g512, 128>>>(NTOK, DD, DD, DD, ATT, Wo, bo, AO, 0);
    add_ln_kernel<<<NTOK, 128>>>(AO, Z, gamma, beta, Aa, 0, 1);

    // 6. FFN
    dim3 gff(DFF / 128, NTOK / 128);
    gemm_tf32_kernel<<<gff, 128>>>(NTOK, DFF, DD, DFF, Aa, W1, b1, H1, 1);
    gemm_tf32_kernel<<<g512, 128>>>(NTOK, DD, DFF, DD, H1, W2, b2, F, 0);

    // 7. residual LN + final relu -> output
    add_ln_kernel<<<NTOK, 128>>>(F, Aa, gamma, beta, out, 1, 0);
}